// round 2
// baseline (speedup 1.0000x reference)
#include <cuda_runtime.h>
#include <math.h>

#define TT    1024
#define BATCH 512
#define DIN   128
#define HIDN  256
#define BB    4
#define NCTA  (BATCH / BB)   /* 128 */
#define NT    256
#define KC    44             /* hh k-rows cached in smem */

// Transposed / interleaved weight scratch (module-load allocated, no runtime alloc).
__device__ float2 g_whh2[HIDN][HIDN];   // [k][j] = (hh_w[j][k], hh_w[j+256][k])  512KB
__device__ float  g_wih_t[DIN][HIDN];   // [k][h] = ih_w[h][k]                    128KB

__global__ void prep_whh_kernel(const float* __restrict__ hh_w) {
    int idx = blockIdx.x * blockDim.x + threadIdx.x;   // 65536 threads
    int j = idx & (HIDN - 1);
    int k = idx >> 8;
    g_whh2[k][j] = make_float2(hh_w[j * HIDN + k], hh_w[(j + HIDN) * HIDN + k]);
}

__global__ void prep_wih_kernel(const float* __restrict__ ih_w) {
    int idx = blockIdx.x * blockDim.x + threadIdx.x;   // 32768 threads
    int h = idx & (HIDN - 1);
    int k = idx >> 8;
    g_wih_t[k][h] = ih_w[h * DIN + k];
}

// smem layout (floats):
//  s_wih  : DIN*HIDN          = 32768  (128KB)
//  s_whh2 : KC*HIDN float2    = 22528  ( 88KB)
//  s_hid  : BB*HIDN           =  1024  (  4KB)
//  s_x    : BB*DIN            =   512  (  2KB)
#define SMEM_FLOATS (DIN * HIDN + KC * HIDN * 2 + BB * HIDN + BB * DIN)
#define SMEM_BYTES  (SMEM_FLOATS * 4)

__global__ __launch_bounds__(NT, 1)
void rnn_kernel(const float* __restrict__ data,
                const float* __restrict__ ih_b,
                const float* __restrict__ hh_b,
                const int*   __restrict__ lengths,
                float*       __restrict__ out)
{
    extern __shared__ float smem[];
    float*  s_wih  = smem;
    float2* s_whh2 = (float2*)(smem + DIN * HIDN);
    float*  s_hid  = smem + DIN * HIDN + KC * HIDN * 2;
    float*  s_x    = s_hid + BB * HIDN;

    const int tid = threadIdx.x;
    const int bg0 = blockIdx.x * BB;

    // Preload weights (coalesced) and zero hidden.
    {
        const float* gw = (const float*)g_wih_t;
        for (int i = tid; i < DIN * HIDN; i += NT) s_wih[i] = gw[i];
        const float2* gw2 = (const float2*)g_whh2;
        for (int i = tid; i < KC * HIDN; i += NT) s_whh2[i] = gw2[i];
        for (int i = tid; i < BB * HIDN; i += NT) s_hid[i] = 0.0f;
    }

    const float bA = hh_b[tid];          // alpha bias (row tid)
    const float bH = hh_b[tid + HIDN];   // h bias     (row tid+256)
    const float bX = ih_b[tid];

    int len[BB];
    int cap = 0;
    #pragma unroll
    for (int b = 0; b < BB; b++) {
        len[b] = lengths[bg0 + b];
        cap = max(cap, len[b]);
    }

    for (int t = 0; t < cap; ++t) {
        // Stage x_t for our BB batches (first 128 threads, one float4 each).
        if (tid < (BB * DIN) / 4) {
            const float4* src = (const float4*)(data + ((size_t)t * BATCH + bg0) * DIN);
            ((float4*)s_x)[tid] = src[tid];
        }
        __syncthreads();   // x staged; previous step's hidden updates visible

        float accA[BB], accH[BB], accX[BB];
        #pragma unroll
        for (int b = 0; b < BB; b++) { accA[b] = 0.f; accH[b] = 0.f; accX[b] = 0.f; }

        // ---- hh part, smem-cached k rows ----
        #pragma unroll 2
        for (int k = 0; k < KC; k += 4) {
            float2 w0 = s_whh2[(k + 0) * HIDN + tid];
            float2 w1 = s_whh2[(k + 1) * HIDN + tid];
            float2 w2 = s_whh2[(k + 2) * HIDN + tid];
            float2 w3 = s_whh2[(k + 3) * HIDN + tid];
            #pragma unroll
            for (int b = 0; b < BB; b++) {
                float4 hv = *(const float4*)&s_hid[b * HIDN + k];
                accA[b] = fmaf(hv.x, w0.x, accA[b]); accH[b] = fmaf(hv.x, w0.y, accH[b]);
                accA[b] = fmaf(hv.y, w1.x, accA[b]); accH[b] = fmaf(hv.y, w1.y, accH[b]);
                accA[b] = fmaf(hv.z, w2.x, accA[b]); accH[b] = fmaf(hv.z, w2.y, accH[b]);
                accA[b] = fmaf(hv.w, w3.x, accA[b]); accH[b] = fmaf(hv.w, w3.y, accH[b]);
            }
        }
        // ---- hh part, L2-streamed k rows ----
        #pragma unroll 2
        for (int k = KC; k < HIDN; k += 4) {
            float2 w0 = g_whh2[k + 0][tid];
            float2 w1 = g_whh2[k + 1][tid];
            float2 w2 = g_whh2[k + 2][tid];
            float2 w3 = g_whh2[k + 3][tid];
            #pragma unroll
            for (int b = 0; b < BB; b++) {
                float4 hv = *(const float4*)&s_hid[b * HIDN + k];
                accA[b] = fmaf(hv.x, w0.x, accA[b]); accH[b] = fmaf(hv.x, w0.y, accH[b]);
                accA[b] = fmaf(hv.y, w1.x, accA[b]); accH[b] = fmaf(hv.y, w1.y, accH[b]);
                accA[b] = fmaf(hv.z, w2.x, accA[b]); accH[b] = fmaf(hv.z, w2.y, accH[b]);
                accA[b] = fmaf(hv.w, w3.x, accA[b]); accH[b] = fmaf(hv.w, w3.y, accH[b]);
            }
        }
        // ---- ih part (weights fully in smem) ----
        #pragma unroll 2
        for (int k = 0; k < DIN; k += 4) {
            float w0 = s_wih[(k + 0) * HIDN + tid];
            float w1 = s_wih[(k + 1) * HIDN + tid];
            float w2 = s_wih[(k + 2) * HIDN + tid];
            float w3 = s_wih[(k + 3) * HIDN + tid];
            #pragma unroll
            for (int b = 0; b < BB; b++) {
                float4 xv = *(const float4*)&s_x[b * DIN + k];
                accX[b] = fmaf(xv.x, w0, accX[b]);
                accX[b] = fmaf(xv.y, w1, accX[b]);
                accX[b] = fmaf(xv.z, w2, accX[b]);
                accX[b] = fmaf(xv.w, w3, accX[b]);
            }
        }
        __syncthreads();   // all reads of s_hid done before updating

        #pragma unroll
        for (int b = 0; b < BB; b++) {
            float araw  = accA[b] + bA;
            float hraw  = accH[b] + bH;
            float alpha = 1.0f / (1.0f + expf(-araw));
            float hs    = (exp2f(alpha * hraw) - 1.0f) / alpha + alpha;
            float nh    = tanhf(accX[b] + bX + hs);
            if (t < len[b]) s_hid[b * HIDN + tid] = nh;   // thread owns column tid
        }
    }

    // Thread tid wrote column tid itself — no sync needed before readback.
    #pragma unroll
    for (int b = 0; b < BB; b++)
        out[(size_t)(bg0 + b) * HIDN + tid] = s_hid[b * HIDN + tid];
}

extern "C" void kernel_launch(void* const* d_in, const int* in_sizes, int n_in,
                              void* d_out, int out_size)
{
    (void)in_sizes; (void)n_in; (void)out_size;
    const float* data    = (const float*)d_in[0];   // [1024,512,128]
    const float* ih_w    = (const float*)d_in[1];   // [256,128]
    const float* ih_b    = (const float*)d_in[2];   // [256]
    const float* hh_w    = (const float*)d_in[3];   // [512,256]
    const float* hh_b    = (const float*)d_in[4];   // [512]
    const int*   lengths = (const int*)d_in[5];     // [512]
    float*       out     = (float*)d_out;           // [1,512,256]

    prep_whh_kernel<<<(HIDN * HIDN) / NT, NT>>>(hh_w);
    prep_wih_kernel<<<(DIN * HIDN) / NT, NT>>>(ih_w);

    cudaFuncSetAttribute(rnn_kernel,
                         cudaFuncAttributeMaxDynamicSharedMemorySize, SMEM_BYTES);
    rnn_kernel<<<NCTA, NT, SMEM_BYTES>>>(data, ih_b, hh_b, lengths, out);
}

// round 4
// speedup vs baseline: 1.1614x; 1.1614x over previous
#include <cuda_runtime.h>
#include <math.h>
#include <stdint.h>

#define TT     1024
#define BATCH  512
#define DIN    128
#define HIDN   256
#define CSIZE  4              /* CTAs per cluster                   */
#define BC     16             /* batches per cluster                */
#define CPC    64             /* hidden cols per CTA                */
#define NCTA   128
#define NT     256

// smem (floats):
//  s_whh : [256 k][64 cl] float2 (wA,wH)            = 131072 B
//  s_wih : [128 k][64 cl] float                     =  32768 B
//  s_hid : [16 b][256 k] float2 dup (h,h)           =  32768 B
//  s_x   : [16 b][128 k] float                      =   8192 B
#define OFF_WHH 0
#define OFF_WIH (OFF_WHH + 256 * 64 * 2)
#define OFF_HID (OFF_WIH + 128 * 64)
#define OFF_X   (OFF_HID + 16 * 512)
#define SMEM_FLOATS (OFF_X + 16 * 128)
#define SMEM_BYTES  (SMEM_FLOATS * 4)   /* 204800 */

typedef unsigned long long ull;

__device__ __forceinline__ ull ffma2(ull a, ull b, ull c) {
    ull d;
    asm("fma.rn.f32x2 %0, %1, %2, %3;" : "=l"(d) : "l"(a), "l"(b), "l"(c));
    return d;
}

__device__ __forceinline__ uint32_t smem_u32(const void* p) {
    uint32_t a;
    asm("{ .reg .u64 t; cvta.to.shared.u64 t, %1; cvt.u32.u64 %0, t; }"
        : "=r"(a) : "l"(p));
    return a;
}

__device__ __forceinline__ void cluster_sync_() {
    asm volatile("barrier.cluster.arrive.aligned;" ::: "memory");
    asm volatile("barrier.cluster.wait.aligned;" ::: "memory");
}

__global__ __launch_bounds__(NT, 1) __cluster_dims__(CSIZE, 1, 1)
void rnn_kernel(const float* __restrict__ data,
                const float* __restrict__ ih_w,
                const float* __restrict__ ih_b,
                const float* __restrict__ hh_w,
                const float* __restrict__ hh_b,
                const int*   __restrict__ lengths,
                float*       __restrict__ out)
{
    extern __shared__ float smem[];
    float* s_whh = smem + OFF_WHH;
    float* s_wih = smem + OFF_WIH;
    float* s_hid = smem + OFF_HID;
    float* s_x   = smem + OFF_X;

    const int tid = threadIdx.x;
    uint32_t r;
    asm("mov.u32 %0, %%cluster_ctarank;" : "=r"(r));
    const int B0  = (blockIdx.x >> 2) * BC;     // first global batch of cluster
    const int cl  = tid & 63;                    // local col
    const int bg  = tid >> 6;                    // batch group 0..3
    const int b0  = bg * 4;                      // first local batch
    const int gc  = (int)r * CPC + cl;           // global hidden col this thread owns

    // ---- one-time weight staging (transpose on the fly, coalesced reads) ----
    for (int idx = tid; idx < CPC * 256; idx += NT) {
        int c2 = idx >> 8, k = idx & 255;
        int g2 = (int)r * CPC + c2;
        float wa = hh_w[g2 * HIDN + k];
        float wh = hh_w[(g2 + HIDN) * HIDN + k];
        *(float2*)&s_whh[(k * 64 + c2) * 2] = make_float2(wa, wh);
    }
    for (int idx = tid; idx < CPC * 128; idx += NT) {
        int c2 = idx >> 7, k = idx & 127;
        s_wih[k * 64 + c2] = ih_w[((int)r * CPC + c2) * DIN + k];
    }
    for (int idx = tid; idx < 16 * 512; idx += NT) s_hid[idx] = 0.0f;

    const float bA = hh_b[gc];
    const float bH = hh_b[gc + HIDN];
    const float bX = ih_b[gc];

    int len[4];
    #pragma unroll
    for (int b = 0; b < 4; b++) len[b] = lengths[B0 + b0 + b];
    int cap = 1;
    for (int i = 0; i < BC; i++) cap = max(cap, lengths[B0 + i]);

    __syncthreads();

    const uint32_t hid_base = smem_u32(s_hid);
    const ull* wp = (const ull*)s_whh + cl;      // stride 64 per k

    // prefetch x(0): thread handles quads tid and tid+256 of [16b][32quads]
    float4 xpre0, xpre1;
    {
        const float4* src = (const float4*)(data + ((size_t)0 * BATCH + B0) * DIN);
        xpre0 = src[tid];
        xpre1 = src[tid + NT];
    }

    for (int t = 0; t < cap; ++t) {
        // stage x_t ([b][k] natural layout, conflict-free float4 stores)
        ((float4*)s_x)[tid]      = xpre0;
        ((float4*)s_x)[tid + NT] = xpre1;
        __syncthreads();
        if (t + 1 < cap) {   // prefetch next x while computing
            const float4* src = (const float4*)(data + ((size_t)(t + 1) * BATCH + B0) * DIN);
            xpre0 = src[tid];
            xpre1 = src[tid + NT];
        }

        ull   acc[4] = {0ull, 0ull, 0ull, 0ull};   // packed (accA, accH)
        float accX[4] = {0.f, 0.f, 0.f, 0.f};

        // ---- hh: 256-k, dup-hidden FFMA2 ----
        #pragma unroll 4
        for (int k = 0; k < 256; k += 2) {
            ull wA = wp[(k + 0) * 64];
            ull wB = wp[(k + 1) * 64];
            #pragma unroll
            for (int b = 0; b < 4; b++) {
                ulonglong2 hd = *(const ulonglong2*)(s_hid + ((b0 + b) * 512 + 2 * k));
                acc[b] = ffma2(hd.x, wA, acc[b]);
                acc[b] = ffma2(hd.y, wB, acc[b]);
            }
        }
        // ---- ih ----
        #pragma unroll 2
        for (int k = 0; k < 128; k += 4) {
            float w0 = s_wih[(k + 0) * 64 + cl];
            float w1 = s_wih[(k + 1) * 64 + cl];
            float w2 = s_wih[(k + 2) * 64 + cl];
            float w3 = s_wih[(k + 3) * 64 + cl];
            #pragma unroll
            for (int b = 0; b < 4; b++) {
                float4 xv = *(const float4*)(s_x + (b0 + b) * 128 + k);
                accX[b] = fmaf(xv.x, w0, accX[b]);
                accX[b] = fmaf(xv.y, w1, accX[b]);
                accX[b] = fmaf(xv.z, w2, accX[b]);
                accX[b] = fmaf(xv.w, w3, accX[b]);
            }
        }

        // epilogue (registers only — before the read/write barrier)
        float nh[4];
        #pragma unroll
        for (int b = 0; b < 4; b++) {
            uint32_t lo = (uint32_t)(acc[b] & 0xffffffffull);
            uint32_t hi = (uint32_t)(acc[b] >> 32);
            float araw  = __uint_as_float(lo) + bA;
            float hraw  = __uint_as_float(hi) + bH;
            float alpha = 1.0f / (1.0f + expf(-araw));
            float hs    = (exp2f(alpha * hraw) - 1.0f) / alpha + alpha;
            nh[b]       = tanhf(accX[b] + bX + hs);
        }

        cluster_sync_();   // all reads of s_hid done cluster-wide

        // broadcast new hidden (duplicated pair) to all 4 CTAs' s_hid
        #pragma unroll
        for (int b = 0; b < 4; b++) {
            if (t < len[b]) {
                uint32_t v = __float_as_uint(nh[b]);
                ull v2;
                asm("mov.b64 %0, {%1, %1};" : "=l"(v2) : "r"(v));
                uint32_t loc = hid_base + (((b0 + b) * 512 + 2 * gc) << 2);
                #pragma unroll
                for (int dst = 0; dst < CSIZE; dst++) {
                    uint32_t ra;
                    asm("mapa.shared::cluster.u32 %0, %1, %2;"
                        : "=r"(ra) : "r"(loc), "r"(dst));
                    asm volatile("st.shared::cluster.u64 [%0], %1;"
                                 :: "r"(ra), "l"(v2) : "memory");
                }
            }
        }

        cluster_sync_();   // writes visible before next step's reads
    }

    // final hidden lives (duplicated) in local s_hid
    #pragma unroll
    for (int b = 0; b < 4; b++)
        out[(size_t)(B0 + b0 + b) * HIDN + gc] = s_hid[(b0 + b) * 512 + 2 * gc];
}

extern "C" void kernel_launch(void* const* d_in, const int* in_sizes, int n_in,
                              void* d_out, int out_size)
{
    (void)in_sizes; (void)n_in; (void)out_size;
    const float* data    = (const float*)d_in[0];   // [1024,512,128]
    const float* ih_w    = (const float*)d_in[1];   // [256,128]
    const float* ih_b    = (const float*)d_in[2];   // [256]
    const float* hh_w    = (const float*)d_in[3];   // [512,256]
    const float* hh_b    = (const float*)d_in[4];   // [512]
    const int*   lengths = (const int*)d_in[5];     // [512]
    float*       out     = (float*)d_out;           // [1,512,256]

    cudaFuncSetAttribute(rnn_kernel,
                         cudaFuncAttributeMaxDynamicSharedMemorySize, SMEM_BYTES);
    rnn_kernel<<<NCTA, NT, SMEM_BYTES>>>(data, ih_w, ih_b, hh_w, hh_b, lengths, out);
}

// round 5
// speedup vs baseline: 1.5029x; 1.2941x over previous
#include <cuda_runtime.h>
#include <math.h>
#include <stdint.h>

#define BATCH 512
#define DIN   128
#define HIDN  256
#define CSIZE 4
#define BC    16
#define CPC   64
#define NCTA  128
#define NT    256

// smem layout (float offsets)
#define OFF_HID0 0            /* [16][256][2] dup hidden, buffer 0 : 32KB */
#define OFF_HID1 8192         /* buffer 1                           : 32KB */
#define OFF_X    16384        /* [16][128] x_t                      :  8KB */
#define OFF_PAH  18432        /* ull [4][16][64] (A,H) partials     : 32KB */
#define OFF_PX   26624        /* float [4][16][64] X partials       : 16KB */
#define SMEM_FLOATS 30720
#define SMEM_BYTES  (SMEM_FLOATS * 4)   /* 122880 */

typedef unsigned long long ull;

__device__ __forceinline__ ull ffma2(ull a, ull b, ull c) {
    ull d;
    asm("fma.rn.f32x2 %0, %1, %2, %3;" : "=l"(d) : "l"(a), "l"(b), "l"(c));
    return d;
}
__device__ __forceinline__ ull add2(ull a, ull b) {
    ull d;
    asm("add.rn.f32x2 %0, %1, %2;" : "=l"(d) : "l"(a), "l"(b));
    return d;
}
__device__ __forceinline__ ull pack2(float x, float y) {
    ull d;
    asm("mov.b64 %0, {%1, %2};" : "=l"(d) : "f"(x), "f"(y));
    return d;
}
__device__ __forceinline__ void unpack2(ull a, float& x, float& y) {
    asm("mov.b64 {%0, %1}, %2;" : "=f"(x), "=f"(y) : "l"(a));
}
__device__ __forceinline__ uint32_t smem_u32(const void* p) {
    uint32_t a;
    asm("{ .reg .u64 t; cvta.to.shared.u64 t, %1; cvt.u32.u64 %0, t; }"
        : "=r"(a) : "l"(p));
    return a;
}
__device__ __forceinline__ void cluster_sync_() {
    asm volatile("barrier.cluster.arrive.aligned;" ::: "memory");
    asm volatile("barrier.cluster.wait.aligned;" ::: "memory");
}

__global__ __launch_bounds__(NT, 1) __cluster_dims__(CSIZE, 1, 1)
void rnn_kernel(const float* __restrict__ data,
                const float* __restrict__ ih_w,
                const float* __restrict__ ih_b,
                const float* __restrict__ hh_w,
                const float* __restrict__ hh_b,
                const int*   __restrict__ lengths,
                float*       __restrict__ out)
{
    extern __shared__ float smem[];
    float* s_x  = smem + OFF_X;
    ull*   s_pAH = (ull*)(smem + OFF_PAH);
    float* s_pX  = smem + OFF_PX;

    const int tid = threadIdx.x;
    uint32_t r;
    asm("mov.u32 %0, %%cluster_ctarank;" : "=r"(r));
    const int B0  = (blockIdx.x >> 2) * BC;
    const int cl  = tid & 63;          // owned column (local)
    const int kq  = tid >> 6;          // k-quarter 0..3
    const int gc  = (int)r * CPC + cl; // global column
    const int k0  = kq * 64;           // hh k range [k0, k0+64)
    const int ik0 = kq * 32;           // ih k range [ik0, ik0+32)

    // ---- persistent register weights ----
    ull whh2[64];                      // (wA[k], wH[k]) for col gc
    #pragma unroll
    for (int i = 0; i < 64; i++) {
        float wa = hh_w[gc * HIDN + k0 + i];
        float wh = hh_w[(gc + HIDN) * HIDN + k0 + i];
        whh2[i] = pack2(wa, wh);
    }
    float wih_r[32];
    #pragma unroll
    for (int i = 0; i < 32; i++) wih_r[i] = ih_w[gc * DIN + ik0 + i];

    // zero both hidden buffers
    for (int i = tid; i < 16384; i += NT) smem[i] = 0.0f;

    const float bA = hh_b[gc];
    const float bH = hh_b[gc + HIDN];
    const float bX = ih_b[gc];

    int len4[4];
    #pragma unroll
    for (int j = 0; j < 4; j++) len4[j] = lengths[B0 + kq * 4 + j];
    int cap = 1;
    for (int i = 0; i < BC; i++) cap = max(cap, lengths[B0 + i]);

    // remote hidden bases (buffer0); buffer1 = +32768 bytes
    uint32_t h0 = smem_u32(smem);
    uint32_t rb[CSIZE];
    #pragma unroll
    for (int d = 0; d < CSIZE; d++)
        asm("mapa.shared::cluster.u32 %0, %1, %2;" : "=r"(rb[d]) : "r"(h0), "r"(d));

    __syncthreads();
    cluster_sync_();   // all CTAs zeroed before any remote write

    // prefetch x(0)
    float4 xp0, xp1;
    {
        const float4* src = (const float4*)(data + ((size_t)0 * BATCH + B0) * DIN);
        xp0 = src[tid];
        xp1 = src[tid + NT];
    }

    for (int t = 0; t < cap; ++t) {
        const float* cur = smem + ((t & 1) ? OFF_HID1 : OFF_HID0);
        const uint32_t nxtoff = ((t + 1) & 1) * 32768u;   // byte offset of next buffer

        // stage x_t
        ((float4*)s_x)[tid]      = xp0;
        ((float4*)s_x)[tid + NT] = xp1;
        __syncthreads();
        if (t + 1 < cap) {
            const float4* src = (const float4*)(data + ((size_t)(t + 1) * BATCH + B0) * DIN);
            xp0 = src[tid];
            xp1 = src[tid + NT];
        }

        // ---- compute partials for all 16 batches ----
        #pragma unroll 2
        for (int b = 0; b < 16; b++) {
            const float* hb = cur + b * 512 + k0 * 2;   // dup layout
            ull a0 = 0ull, a1 = 0ull, a2 = 0ull, a3 = 0ull;
            #pragma unroll
            for (int i = 0; i < 32; i++) {
                ulonglong2 hd = *(const ulonglong2*)(hb + 4 * i);
                if (i & 1) {
                    a2 = ffma2(hd.x, whh2[2 * i],     a2);
                    a3 = ffma2(hd.y, whh2[2 * i + 1], a3);
                } else {
                    a0 = ffma2(hd.x, whh2[2 * i],     a0);
                    a1 = ffma2(hd.y, whh2[2 * i + 1], a1);
                }
            }
            const float* xb = s_x + b * 128 + ik0;
            float x0 = 0.f, x1 = 0.f, x2 = 0.f, x3 = 0.f;
            #pragma unroll
            for (int i = 0; i < 8; i++) {
                float4 xv = *(const float4*)(xb + 4 * i);
                x0 = fmaf(xv.x, wih_r[4 * i + 0], x0);
                x1 = fmaf(xv.y, wih_r[4 * i + 1], x1);
                x2 = fmaf(xv.z, wih_r[4 * i + 2], x2);
                x3 = fmaf(xv.w, wih_r[4 * i + 3], x3);
            }
            s_pAH[(kq * 16 + b) * 64 + cl] = add2(add2(a0, a2), add2(a1, a3));
            s_pX [(kq * 16 + b) * 64 + cl] = (x0 + x1) + (x2 + x3);
        }
        __syncthreads();   // partials visible CTA-locally

        // ---- epilogue: this thread finalizes batches kq*4 .. kq*4+3, col cl ----
        float wval[4];
        #pragma unroll
        for (int j = 0; j < 4; j++) {
            int b = kq * 4 + j;
            ull sAH = s_pAH[(0 * 16 + b) * 64 + cl];
            sAH = add2(sAH, s_pAH[(1 * 16 + b) * 64 + cl]);
            sAH = add2(sAH, s_pAH[(2 * 16 + b) * 64 + cl]);
            sAH = add2(sAH, s_pAH[(3 * 16 + b) * 64 + cl]);
            float sX = s_pX[(0 * 16 + b) * 64 + cl]
                     + s_pX[(1 * 16 + b) * 64 + cl]
                     + s_pX[(2 * 16 + b) * 64 + cl]
                     + s_pX[(3 * 16 + b) * 64 + cl];
            float A, H;
            unpack2(sAH, A, H);
            A += bA; H += bH;
            float alpha = 1.0f / (1.0f + expf(-A));
            float hs    = (exp2f(alpha * H) - 1.0f) / alpha + alpha;
            float nh    = tanhf(sX + bX + hs);
            float oldv  = cur[b * 512 + 2 * gc];          // carry-over for masked rows
            wval[j] = (t < len4[j]) ? nh : oldv;
        }

        // ---- broadcast (dup) to next buffer of all 4 CTAs ----
        #pragma unroll
        for (int j = 0; j < 4; j++) {
            uint32_t v = __float_as_uint(wval[j]);
            ull v2;
            asm("mov.b64 %0, {%1, %1};" : "=l"(v2) : "r"(v));
            uint32_t boff = nxtoff + (uint32_t)(((kq * 4 + j) * 512 + 2 * gc) * 4);
            #pragma unroll
            for (int d = 0; d < CSIZE; d++) {
                asm volatile("st.shared::cluster.u64 [%0], %1;"
                             :: "r"(rb[d] + boff), "l"(v2) : "memory");
            }
        }
        cluster_sync_();   // writes visible before next step's reads
    }

    // final state lives in buffer (cap & 1)
    const float* fin = smem + ((cap & 1) ? OFF_HID1 : OFF_HID0);
    #pragma unroll
    for (int j = 0; j < 4; j++) {
        int b = kq * 4 + j;
        out[(size_t)(B0 + b) * HIDN + gc] = fin[b * 512 + 2 * gc];
    }
}

extern "C" void kernel_launch(void* const* d_in, const int* in_sizes, int n_in,
                              void* d_out, int out_size)
{
    (void)in_sizes; (void)n_in; (void)out_size;
    const float* data    = (const float*)d_in[0];   // [1024,512,128]
    const float* ih_w    = (const float*)d_in[1];   // [256,128]
    const float* ih_b    = (const float*)d_in[2];   // [256]
    const float* hh_w    = (const float*)d_in[3];   // [512,256]
    const float* hh_b    = (const float*)d_in[4];   // [512]
    const int*   lengths = (const int*)d_in[5];     // [512]
    float*       out     = (float*)d_out;           // [1,512,256]

    cudaFuncSetAttribute(rnn_kernel,
                         cudaFuncAttributeMaxDynamicSharedMemorySize, SMEM_BYTES);
    rnn_kernel<<<NCTA, NT, SMEM_BYTES>>>(data, ih_w, ih_b, hh_w, hh_b, lengths, out);
}